// round 1
// baseline (speedup 1.0000x reference)
#include <cuda_runtime.h>
#include <math.h>

// ---------------- problem constants ----------------
#define BB 128
#define CC 3
#define IMG 224
#define PP 16
#define HP 14          // IMG/PP
#define NP 196         // HP*HP
#define SS 197         // 1+NP
#define DD 384
#define HEADS 6
#define HD 64
#define DEPTH 12
#define HID 1536
#define NCLS 100
#define PATCH_DIM 768  // C*P*P
#define TOK (BB*SS)    // 25216
#define PTOK (BB*NP)   // 25088
#define BH (BB*HEADS)  // 768

// ---------------- scratch (static device globals; allocation-free) ----------------
__device__ float g_patches[PTOK * PATCH_DIM];   // 19,267,584
__device__ float g_tok[PTOK * DD];              //  9,633,792
__device__ float g_h[TOK * DD];                 //  9,682,944
__device__ float g_xn[TOK * DD];                //  9,682,944
__device__ float g_qkv[TOK * 3 * DD];           // 29,048,832
__device__ float g_scores[(size_t)BH * SS * SS];// 29,805,312
__device__ float g_ctx[TOK * DD];               //  9,682,944
__device__ float g_hid[TOK * HID];              // 38,731,776
__device__ float g_cls[BB * DD];                //     49,152

// ---------------- patchify: x[B,C,224,224] -> patches[B*196, 768] ----------------
__global__ void patchify_kernel(const float* __restrict__ x, float* __restrict__ patches) {
    int idx = blockIdx.x * blockDim.x + threadIdx.x;
    if (idx >= PTOK * PATCH_DIM) return;
    int t = idx / PATCH_DIM;
    int k = idx - t * PATCH_DIM;
    int b = t / NP;
    int n = t - b * NP;
    int ph = n / HP, pw = n - ph * HP;
    int c = k >> 8;            // /256
    int py = (k >> 4) & 15;
    int px = k & 15;
    patches[idx] = x[(((size_t)b * CC + c) * IMG + (ph * PP + py)) * IMG + (pw * PP + px)];
}

// ---------------- assemble h = [cls; tok] + pos ----------------
__global__ void assemble_kernel(const float* __restrict__ tok, const float* __restrict__ cls_token,
                                const float* __restrict__ pos, float* __restrict__ h) {
    int idx = blockIdx.x * blockDim.x + threadIdx.x;
    if (idx >= TOK * DD) return;
    int row = idx / DD;
    int d = idx - row * DD;
    int b = row / SS;
    int s = row - b * SS;
    float v = (s == 0) ? cls_token[d] : tok[((size_t)b * NP + (s - 1)) * DD + d];
    h[idx] = v + pos[s * DD + d];
}

// ---------------- generic NT GEMM: C[M,N] = op(A[M,K] * B[N,K]^T + bias [+res]) ----------------
// Requires M%64==0, N%64==0, K%16==0. OP: 0=bias, 1=bias+gelu(exact), 2=bias+residual
template <int OP>
__global__ void __launch_bounds__(256) gemm_nt_kernel(
    const float* __restrict__ A, const float* __restrict__ Bw,
    const float* __restrict__ bias, const float* __restrict__ res,
    float* __restrict__ C, int M, int N, int K)
{
    __shared__ __align__(16) float As[16][64];
    __shared__ __align__(16) float Bs[16][64];
    const int tid = threadIdx.x;
    const int tx = tid & 15, ty = tid >> 4;
    const int m0 = blockIdx.y * 64, n0 = blockIdx.x * 64;
    const float* Ab = A + (size_t)m0 * K;
    const float* Bb = Bw + (size_t)n0 * K;
    const int r = tid >> 2;          // 0..63
    const int c4 = (tid & 3) * 4;    // 0,4,8,12

    float acc[4][4];
#pragma unroll
    for (int i = 0; i < 4; i++)
#pragma unroll
        for (int j = 0; j < 4; j++) acc[i][j] = 0.f;

    for (int k0 = 0; k0 < K; k0 += 16) {
        float4 av = *(const float4*)(Ab + (size_t)r * K + k0 + c4);
        float4 bv = *(const float4*)(Bb + (size_t)r * K + k0 + c4);
        As[c4 + 0][r] = av.x; As[c4 + 1][r] = av.y; As[c4 + 2][r] = av.z; As[c4 + 3][r] = av.w;
        Bs[c4 + 0][r] = bv.x; Bs[c4 + 1][r] = bv.y; Bs[c4 + 2][r] = bv.z; Bs[c4 + 3][r] = bv.w;
        __syncthreads();
#pragma unroll
        for (int k = 0; k < 16; k++) {
            float4 a4 = *(const float4*)&As[k][ty * 4];
            float4 b4 = *(const float4*)&Bs[k][tx * 4];
            float a[4] = {a4.x, a4.y, a4.z, a4.w};
            float b[4] = {b4.x, b4.y, b4.z, b4.w};
#pragma unroll
            for (int i = 0; i < 4; i++)
#pragma unroll
                for (int j = 0; j < 4; j++) acc[i][j] += a[i] * b[j];
        }
        __syncthreads();
    }

    float4 biv = *(const float4*)(bias + n0 + tx * 4);
    float bi[4] = {biv.x, biv.y, biv.z, biv.w};
#pragma unroll
    for (int i = 0; i < 4; i++) {
        int row = m0 + ty * 4 + i;
        float* cp = C + (size_t)row * N + n0 + tx * 4;
        float o[4];
#pragma unroll
        for (int j = 0; j < 4; j++) o[j] = acc[i][j] + bi[j];
        if (OP == 1) {
#pragma unroll
            for (int j = 0; j < 4; j++)
                o[j] = 0.5f * o[j] * (1.0f + erff(o[j] * 0.7071067811865475f));
        }
        if (OP == 2) {
            const float4 rv = *(const float4*)(res + (size_t)row * N + n0 + tx * 4);
            o[0] += rv.x; o[1] += rv.y; o[2] += rv.z; o[3] += rv.w;
        }
        *(float4*)cp = make_float4(o[0], o[1], o[2], o[3]);
    }
}

// ---------------- LayerNorm: one block (384 threads) per row ----------------
__global__ void ln_kernel(const float* __restrict__ x, const float* __restrict__ g,
                          const float* __restrict__ bt, float* __restrict__ y,
                          long in_row_stride)
{
    const int row = blockIdx.x;
    const int tid = threadIdx.x;
    const float* xr = x + (size_t)row * in_row_stride;
    float v = xr[tid];
    float s = v, q = v * v;
#pragma unroll
    for (int o = 16; o; o >>= 1) {
        s += __shfl_down_sync(0xffffffffu, s, o);
        q += __shfl_down_sync(0xffffffffu, q, o);
    }
    __shared__ float sh[12], sh2[12];
    int w = tid >> 5, lane = tid & 31;
    if (lane == 0) { sh[w] = s; sh2[w] = q; }
    __syncthreads();
    if (tid < 32) {
        float ss = (tid < 12) ? sh[tid] : 0.f;
        float qq = (tid < 12) ? sh2[tid] : 0.f;
#pragma unroll
        for (int o = 16; o; o >>= 1) {
            ss += __shfl_down_sync(0xffffffffu, ss, o);
            qq += __shfl_down_sync(0xffffffffu, qq, o);
        }
        if (tid == 0) {
            float mean = ss * (1.0f / DD);
            float var = qq * (1.0f / DD) - mean * mean;
            sh[0] = mean;
            sh2[0] = rsqrtf(var + 1e-5f);
        }
    }
    __syncthreads();
    float mean = sh[0], rstd = sh2[0];
    y[(size_t)row * DD + tid] = (v - mean) * rstd * g[tid] + bt[tid];
}

// ---------------- attention scores: scores[bh,i,j] = scale * q_i . k_j ----------------
__global__ void __launch_bounds__(256) attn_scores_kernel(const float* __restrict__ qkv,
                                                          float* __restrict__ scores)
{
    const int bh = blockIdx.z;
    const int b = bh / HEADS, h = bh - b * HEADS;
    const int i0 = blockIdx.y * 64, j0 = blockIdx.x * 64;
    __shared__ float Qs[64][65];
    __shared__ float Ks[64][65];
    const float* base = qkv + (size_t)b * SS * (3 * DD) + h * HD;
    for (int idx = threadIdx.x; idx < 4096; idx += 256) {
        int ii = idx >> 6, d = idx & 63;
        int i = i0 + ii;
        Qs[ii][d] = (i < SS) ? base[(size_t)i * (3 * DD) + d] * 0.125f : 0.f;
        int j = j0 + ii;
        Ks[ii][d] = (j < SS) ? base[(size_t)j * (3 * DD) + DD + d] : 0.f;
    }
    __syncthreads();
    const int tx = threadIdx.x & 15, ty = threadIdx.x >> 4;
    float acc[4][4];
#pragma unroll
    for (int i = 0; i < 4; i++)
#pragma unroll
        for (int j = 0; j < 4; j++) acc[i][j] = 0.f;
#pragma unroll 8
    for (int d = 0; d < 64; d++) {
        float a[4], bb[4];
#pragma unroll
        for (int r = 0; r < 4; r++) a[r] = Qs[ty * 4 + r][d];
#pragma unroll
        for (int c = 0; c < 4; c++) bb[c] = Ks[tx * 4 + c][d];
#pragma unroll
        for (int r = 0; r < 4; r++)
#pragma unroll
            for (int c = 0; c < 4; c++) acc[r][c] += a[r] * bb[c];
    }
#pragma unroll
    for (int r = 0; r < 4; r++) {
        int i = i0 + ty * 4 + r;
        if (i >= SS) continue;
#pragma unroll
        for (int c = 0; c < 4; c++) {
            int j = j0 + tx * 4 + c;
            if (j < SS) scores[((size_t)bh * SS + i) * SS + j] = acc[r][c];
        }
    }
}

// ---------------- softmax: one warp per row (len 197) ----------------
__global__ void softmax_kernel(float* __restrict__ scores, int nrows) {
    int row = blockIdx.x * 8 + (threadIdx.x >> 5);
    if (row >= nrows) return;
    int lane = threadIdx.x & 31;
    float* p = scores + (size_t)row * SS;
    float vals[7];
    float m = -1e30f;
#pragma unroll
    for (int t = 0; t < 7; t++) {
        int j = lane + 32 * t;
        vals[t] = (j < SS) ? p[j] : -1e30f;
        m = fmaxf(m, vals[t]);
    }
#pragma unroll
    for (int o = 16; o; o >>= 1) m = fmaxf(m, __shfl_xor_sync(0xffffffffu, m, o));
    float s = 0.f;
#pragma unroll
    for (int t = 0; t < 7; t++) {
        int j = lane + 32 * t;
        float e = (j < SS) ? expf(vals[t] - m) : 0.f;
        vals[t] = e;
        s += e;
    }
#pragma unroll
    for (int o = 16; o; o >>= 1) s += __shfl_xor_sync(0xffffffffu, s, o);
    float inv = 1.0f / s;
#pragma unroll
    for (int t = 0; t < 7; t++) {
        int j = lane + 32 * t;
        if (j < SS) p[j] = vals[t] * inv;
    }
}

// ---------------- ctx = attn @ v, written as [b, s, h*64+d] ----------------
__global__ void __launch_bounds__(256) attn_ctx_kernel(const float* __restrict__ scores,
                                                       const float* __restrict__ qkv,
                                                       float* __restrict__ ctx)
{
    const int bh = blockIdx.y;
    const int b = bh / HEADS, h = bh - b * HEADS;
    const int i0 = blockIdx.x * 64;
    __shared__ float As[64][33];
    __shared__ __align__(16) float Vs[32][64];
    const int tx = threadIdx.x & 15, ty = threadIdx.x >> 4;
    const float* vbase = qkv + (size_t)b * SS * (3 * DD) + 2 * DD + h * HD;
    float acc[4][4];
#pragma unroll
    for (int i = 0; i < 4; i++)
#pragma unroll
        for (int j = 0; j < 4; j++) acc[i][j] = 0.f;

    for (int kt = 0; kt < 7; kt++) {
        int jb = kt * 32;
        for (int idx = threadIdx.x; idx < 2048; idx += 256) {
            int ii = idx >> 5, k = idx & 31;
            int i = i0 + ii, j = jb + k;
            As[ii][k] = (i < SS && j < SS) ? scores[((size_t)bh * SS + i) * SS + j] : 0.f;
        }
        for (int idx = threadIdx.x; idx < 2048; idx += 256) {
            int k = idx >> 6, d = idx & 63;
            int j = jb + k;
            Vs[k][d] = (j < SS) ? vbase[(size_t)j * (3 * DD) + d] : 0.f;
        }
        __syncthreads();
#pragma unroll 8
        for (int k = 0; k < 32; k++) {
            float4 b4 = *(const float4*)&Vs[k][tx * 4];
            float bb[4] = {b4.x, b4.y, b4.z, b4.w};
            float a[4];
#pragma unroll
            for (int r = 0; r < 4; r++) a[r] = As[ty * 4 + r][k];
#pragma unroll
            for (int r = 0; r < 4; r++)
#pragma unroll
                for (int c = 0; c < 4; c++) acc[r][c] += a[r] * bb[c];
        }
        __syncthreads();
    }
#pragma unroll
    for (int r = 0; r < 4; r++) {
        int i = i0 + ty * 4 + r;
        if (i < SS) {
            float4 o = make_float4(acc[r][0], acc[r][1], acc[r][2], acc[r][3]);
            *(float4*)&ctx[((size_t)b * SS + i) * DD + h * HD + tx * 4] = o;
        }
    }
}

// ---------------- classifier head: out[b,c] = cls[b,:] . head_w[c,:] ----------------
__global__ void head_kernel(const float* __restrict__ cls, const float* __restrict__ hw,
                            float* __restrict__ out)
{
    __shared__ float s[DD];
    int b = blockIdx.x;
    for (int k = threadIdx.x; k < DD; k += blockDim.x) s[k] = cls[(size_t)b * DD + k];
    __syncthreads();
    int c = threadIdx.x;
    if (c < NCLS) {
        const float* w = hw + (size_t)c * DD;
        float acc = 0.f;
#pragma unroll 8
        for (int k = 0; k < DD; k++) acc += s[k] * w[k];
        out[(size_t)b * NCLS + c] = acc;
    }
}

// ---------------- launch ----------------
extern "C" void kernel_launch(void* const* d_in, const int* in_sizes, int n_in,
                              void* d_out, int out_size) {
    const float* x         = (const float*)d_in[0];
    const float* patch_w   = (const float*)d_in[1];
    const float* patch_b   = (const float*)d_in[2];
    const float* cls_token = (const float*)d_in[3];
    const float* pos_embed = (const float*)d_in[4];
    const float* ln1_g     = (const float*)d_in[5];
    const float* ln1_b     = (const float*)d_in[6];
    const float* qkv_w     = (const float*)d_in[7];
    const float* qkv_b     = (const float*)d_in[8];
    const float* out_w     = (const float*)d_in[9];
    const float* out_b     = (const float*)d_in[10];
    const float* ln2_g     = (const float*)d_in[11];
    const float* ln2_b     = (const float*)d_in[12];
    const float* fc1_w     = (const float*)d_in[13];
    const float* fc1_b     = (const float*)d_in[14];
    const float* fc2_w     = (const float*)d_in[15];
    const float* fc2_b     = (const float*)d_in[16];
    const float* lnf_g     = (const float*)d_in[17];
    const float* lnf_b     = (const float*)d_in[18];
    const float* head_w    = (const float*)d_in[19];
    float* out = (float*)d_out;

    float *patches, *tok, *h, *xn, *qkv, *scores, *ctx, *hid, *cls;
    cudaGetSymbolAddress((void**)&patches, g_patches);
    cudaGetSymbolAddress((void**)&tok, g_tok);
    cudaGetSymbolAddress((void**)&h, g_h);
    cudaGetSymbolAddress((void**)&xn, g_xn);
    cudaGetSymbolAddress((void**)&qkv, g_qkv);
    cudaGetSymbolAddress((void**)&scores, g_scores);
    cudaGetSymbolAddress((void**)&ctx, g_ctx);
    cudaGetSymbolAddress((void**)&hid, g_hid);
    cudaGetSymbolAddress((void**)&cls, g_cls);

    // patch embedding
    patchify_kernel<<<(PTOK * PATCH_DIM + 255) / 256, 256>>>(x, patches);
    gemm_nt_kernel<0><<<dim3(DD / 64, PTOK / 64), 256>>>(
        patches, patch_w, patch_b, nullptr, tok, PTOK, DD, PATCH_DIM);
    assemble_kernel<<<(TOK * DD + 255) / 256, 256>>>(tok, cls_token, pos_embed, h);

    for (int i = 0; i < DEPTH; i++) {
        // ln1 -> xn
        ln_kernel<<<TOK, DD>>>(h, ln1_g + i * DD, ln1_b + i * DD, xn, DD);
        // qkv = xn @ qkv_w^T + b
        gemm_nt_kernel<0><<<dim3(3 * DD / 64, TOK / 64), 256>>>(
            xn, qkv_w + (size_t)i * 3 * DD * DD, qkv_b + (size_t)i * 3 * DD,
            nullptr, qkv, TOK, 3 * DD, DD);
        // attention
        attn_scores_kernel<<<dim3(4, 4, BH), 256>>>(qkv, scores);
        softmax_kernel<<<(BH * SS + 7) / 8, 256>>>(scores, BH * SS);
        attn_ctx_kernel<<<dim3(4, BH), 256>>>(scores, qkv, ctx);
        // h += ctx @ out_w^T + b
        gemm_nt_kernel<2><<<dim3(DD / 64, TOK / 64), 256>>>(
            ctx, out_w + (size_t)i * DD * DD, out_b + (size_t)i * DD, h, h, TOK, DD, DD);
        // ln2 -> xn
        ln_kernel<<<TOK, DD>>>(h, ln2_g + i * DD, ln2_b + i * DD, xn, DD);
        // hid = gelu(xn @ fc1^T + b)
        gemm_nt_kernel<1><<<dim3(HID / 64, TOK / 64), 256>>>(
            xn, fc1_w + (size_t)i * HID * DD, fc1_b + (size_t)i * HID,
            nullptr, hid, TOK, HID, DD);
        // h += hid @ fc2^T + b
        gemm_nt_kernel<2><<<dim3(DD / 64, TOK / 64), 256>>>(
            hid, fc2_w + (size_t)i * DD * HID, fc2_b + (size_t)i * DD, h, h, TOK, DD, HID);
    }

    // final LN on cls token rows (stride SS*DD), then head
    ln_kernel<<<BB, DD>>>(h, lnf_g, lnf_b, cls, (long)SS * DD);
    head_kernel<<<BB, 128>>>(cls, head_w, out);
}

// round 2
// speedup vs baseline: 2.4723x; 2.4723x over previous
#include <cuda_runtime.h>
#include <math.h>
#include <stdint.h>

// ---------------- problem constants ----------------
#define BB 128
#define CC 3
#define IMG 224
#define PP 16
#define HP 14
#define NP 196
#define SS 197
#define DD 384
#define HEADS 6
#define HD 64
#define DEPTH 12
#define HID 1536
#define NCLS 100
#define PATCH_DIM 768
#define TOK (BB*SS)    // 25216 = 197*128
#define PTOK (BB*NP)   // 25088 = 196*128
#define BH (BB*HEADS)  // 768

// ---------------- scratch ----------------
__device__ float g_patches[PTOK * PATCH_DIM];
__device__ float g_tok[PTOK * DD];
__device__ float g_h[TOK * DD];
__device__ float g_xn[TOK * DD];
__device__ float g_qkv[TOK * 3 * DD];
__device__ float g_scores[(size_t)BH * SS * SS];
__device__ float g_ctx[TOK * DD];
__device__ float g_hid[TOK * HID];
__device__ float g_cls[BB * DD];
// tf32-rounded weights
#define W_PATCH 0
#define W_QKV   294912
#define W_OUT   5603328
#define W_FC1   7372800
#define W_FC2   14450688
#define W_TOTAL 21528576
__device__ float g_w[W_TOTAL];

// ---------------- helpers ----------------
__device__ __forceinline__ float tf32r(float x) {
    uint32_t u;
    asm("cvt.rna.tf32.f32 %0, %1;" : "=r"(u) : "f"(x));
    return __uint_as_float(u);
}
__device__ __forceinline__ uint32_t smem_u32(const void* p) {
    return (uint32_t)__cvta_generic_to_shared(p);
}
#define CPA(dst, src) asm volatile("cp.async.cg.shared.global [%0], [%1], 16;" :: "r"(dst), "l"(src))
#define CPC() asm volatile("cp.async.commit_group;")
#define CPW0() asm volatile("cp.async.wait_group 0;")
#define CPW1() asm volatile("cp.async.wait_group 1;")
#define MMA_TF32(d, a, b) asm volatile( \
    "mma.sync.aligned.m16n8k8.row.col.f32.tf32.tf32.f32 " \
    "{%0,%1,%2,%3},{%4,%5,%6,%7},{%8,%9},{%0,%1,%2,%3};" \
    : "+f"(d[0]), "+f"(d[1]), "+f"(d[2]), "+f"(d[3]) \
    : "r"(a[0]), "r"(a[1]), "r"(a[2]), "r"(a[3]), "r"(b[0]), "r"(b[1]))

// ---------------- weight rounding (tf32, once per launch) ----------------
__global__ void round4_kernel(const float* __restrict__ x, float* __restrict__ y, int n4) {
    int i = blockIdx.x * blockDim.x + threadIdx.x;
    if (i >= n4) return;
    float4 v = ((const float4*)x)[i];
    v.x = tf32r(v.x); v.y = tf32r(v.y); v.z = tf32r(v.z); v.w = tf32r(v.w);
    ((float4*)y)[i] = v;
}

// ---------------- patchify (+tf32 round: feeds patch GEMM) ----------------
__global__ void patchify_kernel(const float* __restrict__ x, float* __restrict__ patches) {
    int idx = blockIdx.x * blockDim.x + threadIdx.x;
    if (idx >= PTOK * PATCH_DIM) return;
    int t = idx / PATCH_DIM;
    int k = idx - t * PATCH_DIM;
    int b = t / NP;
    int n = t - b * NP;
    int ph = n / HP, pw = n - ph * HP;
    int c = k >> 8;
    int py = (k >> 4) & 15;
    int px = k & 15;
    patches[idx] = tf32r(x[(((size_t)b * CC + c) * IMG + (ph * PP + py)) * IMG + (pw * PP + px)]);
}

// ---------------- assemble h = [cls; tok] + pos ----------------
__global__ void assemble_kernel(const float* __restrict__ tok, const float* __restrict__ cls_token,
                                const float* __restrict__ pos, float* __restrict__ h) {
    int idx = blockIdx.x * blockDim.x + threadIdx.x;
    if (idx >= TOK * DD) return;
    int row = idx / DD;
    int d = idx - row * DD;
    int b = row / SS;
    int s = row - b * SS;
    float v = (s == 0) ? cls_token[d] : tok[((size_t)b * NP + (s - 1)) * DD + d];
    h[idx] = v + pos[s * DD + d];
}

// ---------------- tf32 tensor-core NT GEMM ----------------
// C[M,N] = op(A[M,K] * B[N,K]^T + bias [+res]); A,B pre-rounded to tf32 values.
// M%128==0, N%128==0, K%16==0. OP: 0=bias, 1=bias+gelu+round, 2=bias+residual
#define BMT 128
#define BNT 128
#define BKT 16
#define SST 20   // smem row stride (floats): conflict-free fragment LDS

template <int OP>
__global__ void __launch_bounds__(256) gemm_tf32(
    const float* __restrict__ A, const float* __restrict__ Bw,
    const float* __restrict__ bias, const float* __restrict__ res,
    float* __restrict__ C, int M, int N, int K)
{
    __shared__ __align__(16) float As[2][BMT][SST];
    __shared__ __align__(16) float Bs[2][BMT][SST];

    const int tid = threadIdx.x;
    const int lane = tid & 31, warp = tid >> 5;
    const int wm = (warp >> 1) * 32;     // warp row offset (4 row-groups)
    const int wn = (warp & 1) * 64;      // warp col offset (2 col-groups)
    const int r = lane >> 2, cq = lane & 3;
    const int m0 = blockIdx.y * BMT, n0 = blockIdx.x * BNT;

    // global load setup: each thread cp.asyncs 4 x 16B per stage
    const int lrow = tid >> 2;           // 0..63
    const int lcol = (tid & 3) * 4;      // 0,4,8,12
    const float* Ag0 = A + (size_t)(m0 + lrow) * K + lcol;
    const float* Ag1 = A + (size_t)(m0 + lrow + 64) * K + lcol;
    const float* Bg0 = Bw + (size_t)(n0 + lrow) * K + lcol;
    const float* Bg1 = Bw + (size_t)(n0 + lrow + 64) * K + lcol;
    uint32_t dA0[2], dA1[2], dB0[2], dB1[2];
#pragma unroll
    for (int s = 0; s < 2; s++) {
        dA0[s] = smem_u32(&As[s][lrow][lcol]);
        dA1[s] = smem_u32(&As[s][lrow + 64][lcol]);
        dB0[s] = smem_u32(&Bs[s][lrow][lcol]);
        dB1[s] = smem_u32(&Bs[s][lrow + 64][lcol]);
    }

    float acc[2][8][4];
#pragma unroll
    for (int mt = 0; mt < 2; mt++)
#pragma unroll
        for (int nt = 0; nt < 8; nt++)
#pragma unroll
            for (int i = 0; i < 4; i++) acc[mt][nt][i] = 0.f;

    const int KT = K / BKT;
    // prologue
    CPA(dA0[0], Ag0); CPA(dA1[0], Ag1); CPA(dB0[0], Bg0); CPA(dB1[0], Bg1);
    CPC();

    for (int kt = 0; kt < KT; kt++) {
        const int buf = kt & 1;
        if (kt + 1 < KT) {
            const int nb = buf ^ 1;
            const int ko = (kt + 1) * BKT;
            CPA(dA0[nb], Ag0 + ko); CPA(dA1[nb], Ag1 + ko);
            CPA(dB0[nb], Bg0 + ko); CPA(dB1[nb], Bg1 + ko);
            CPC();
            CPW1();
        } else {
            CPW0();
        }
        __syncthreads();

#pragma unroll
        for (int ks = 0; ks < 2; ks++) {
            const int k0 = ks * 8;
            uint32_t a[2][4], b[8][2];
#pragma unroll
            for (int mt = 0; mt < 2; mt++) {
                const float* ap = &As[buf][wm + mt * 16 + r][k0 + cq];
                a[mt][0] = __float_as_uint(ap[0]);
                a[mt][1] = __float_as_uint(ap[8 * SST]);
                a[mt][2] = __float_as_uint(ap[4]);
                a[mt][3] = __float_as_uint(ap[8 * SST + 4]);
            }
#pragma unroll
            for (int nt = 0; nt < 8; nt++) {
                const float* bp = &Bs[buf][wn + nt * 8 + r][k0 + cq];
                b[nt][0] = __float_as_uint(bp[0]);
                b[nt][1] = __float_as_uint(bp[4]);
            }
#pragma unroll
            for (int mt = 0; mt < 2; mt++)
#pragma unroll
                for (int nt = 0; nt < 8; nt++)
                    MMA_TF32(acc[mt][nt], a[mt], b[nt]);
        }
        __syncthreads();
    }

    // epilogue
#pragma unroll
    for (int mt = 0; mt < 2; mt++) {
        const int row = m0 + wm + mt * 16 + r;
#pragma unroll
        for (int nt = 0; nt < 8; nt++) {
            const int col = n0 + wn + nt * 8 + cq * 2;
            const float2 bv = *(const float2*)(bias + col);
            float o0 = acc[mt][nt][0] + bv.x;
            float o1 = acc[mt][nt][1] + bv.y;
            float o2 = acc[mt][nt][2] + bv.x;
            float o3 = acc[mt][nt][3] + bv.y;
            if (OP == 1) {
                o0 = tf32r(0.5f * o0 * (1.0f + erff(o0 * 0.7071067811865475f)));
                o1 = tf32r(0.5f * o1 * (1.0f + erff(o1 * 0.7071067811865475f)));
                o2 = tf32r(0.5f * o2 * (1.0f + erff(o2 * 0.7071067811865475f)));
                o3 = tf32r(0.5f * o3 * (1.0f + erff(o3 * 0.7071067811865475f)));
            }
            if (OP == 2) {
                const float2 r0 = *(const float2*)(res + (size_t)row * N + col);
                const float2 r1 = *(const float2*)(res + (size_t)(row + 8) * N + col);
                o0 += r0.x; o1 += r0.y; o2 += r1.x; o3 += r1.y;
            }
            *(float2*)(C + (size_t)row * N + col) = make_float2(o0, o1);
            *(float2*)(C + (size_t)(row + 8) * N + col) = make_float2(o2, o3);
        }
    }
}

// ---------------- LayerNorm (output tf32-rounded: feeds GEMMs) ----------------
__global__ void ln_kernel(const float* __restrict__ x, const float* __restrict__ g,
                          const float* __restrict__ bt, float* __restrict__ y,
                          long in_row_stride)
{
    const int row = blockIdx.x;
    const int tid = threadIdx.x;
    const float* xr = x + (size_t)row * in_row_stride;
    float v = xr[tid];
    float s = v, q = v * v;
#pragma unroll
    for (int o = 16; o; o >>= 1) {
        s += __shfl_down_sync(0xffffffffu, s, o);
        q += __shfl_down_sync(0xffffffffu, q, o);
    }
    __shared__ float sh[12], sh2[12];
    int w = tid >> 5, lane = tid & 31;
    if (lane == 0) { sh[w] = s; sh2[w] = q; }
    __syncthreads();
    if (tid < 32) {
        float ss = (tid < 12) ? sh[tid] : 0.f;
        float qq = (tid < 12) ? sh2[tid] : 0.f;
#pragma unroll
        for (int o = 16; o; o >>= 1) {
            ss += __shfl_down_sync(0xffffffffu, ss, o);
            qq += __shfl_down_sync(0xffffffffu, qq, o);
        }
        if (tid == 0) {
            float mean = ss * (1.0f / DD);
            float var = qq * (1.0f / DD) - mean * mean;
            sh[0] = mean;
            sh2[0] = rsqrtf(var + 1e-5f);
        }
    }
    __syncthreads();
    float mean = sh[0], rstd = sh2[0];
    y[(size_t)row * DD + tid] = tf32r((v - mean) * rstd * g[tid] + bt[tid]);
}

// ---------------- attention scores ----------------
__global__ void __launch_bounds__(256) attn_scores_kernel(const float* __restrict__ qkv,
                                                          float* __restrict__ scores)
{
    const int bh = blockIdx.z;
    const int b = bh / HEADS, h = bh - b * HEADS;
    const int i0 = blockIdx.y * 64, j0 = blockIdx.x * 64;
    __shared__ float Qs[64][65];
    __shared__ float Ks[64][65];
    const float* base = qkv + (size_t)b * SS * (3 * DD) + h * HD;
    for (int idx = threadIdx.x; idx < 4096; idx += 256) {
        int ii = idx >> 6, d = idx & 63;
        int i = i0 + ii;
        Qs[ii][d] = (i < SS) ? base[(size_t)i * (3 * DD) + d] * 0.125f : 0.f;
        int j = j0 + ii;
        Ks[ii][d] = (j < SS) ? base[(size_t)j * (3 * DD) + DD + d] : 0.f;
    }
    __syncthreads();
    const int tx = threadIdx.x & 15, ty = threadIdx.x >> 4;
    float acc[4][4];
#pragma unroll
    for (int i = 0; i < 4; i++)
#pragma unroll
        for (int j = 0; j < 4; j++) acc[i][j] = 0.f;
#pragma unroll 8
    for (int d = 0; d < 64; d++) {
        float a[4], bb[4];
#pragma unroll
        for (int rr = 0; rr < 4; rr++) a[rr] = Qs[ty * 4 + rr][d];
#pragma unroll
        for (int cc = 0; cc < 4; cc++) bb[cc] = Ks[tx * 4 + cc][d];
#pragma unroll
        for (int rr = 0; rr < 4; rr++)
#pragma unroll
            for (int cc = 0; cc < 4; cc++) acc[rr][cc] += a[rr] * bb[cc];
    }
#pragma unroll
    for (int rr = 0; rr < 4; rr++) {
        int i = i0 + ty * 4 + rr;
        if (i >= SS) continue;
#pragma unroll
        for (int cc = 0; cc < 4; cc++) {
            int j = j0 + tx * 4 + cc;
            if (j < SS) scores[((size_t)bh * SS + i) * SS + j] = acc[rr][cc];
        }
    }
}

// ---------------- softmax ----------------
__global__ void softmax_kernel(float* __restrict__ scores, int nrows) {
    int row = blockIdx.x * 8 + (threadIdx.x >> 5);
    if (row >= nrows) return;
    int lane = threadIdx.x & 31;
    float* p = scores + (size_t)row * SS;
    float vals[7];
    float m = -1e30f;
#pragma unroll
    for (int t = 0; t < 7; t++) {
        int j = lane + 32 * t;
        vals[t] = (j < SS) ? p[j] : -1e30f;
        m = fmaxf(m, vals[t]);
    }
#pragma unroll
    for (int o = 16; o; o >>= 1) m = fmaxf(m, __shfl_xor_sync(0xffffffffu, m, o));
    float s = 0.f;
#pragma unroll
    for (int t = 0; t < 7; t++) {
        int j = lane + 32 * t;
        float e = (j < SS) ? expf(vals[t] - m) : 0.f;
        vals[t] = e;
        s += e;
    }
#pragma unroll
    for (int o = 16; o; o >>= 1) s += __shfl_xor_sync(0xffffffffu, s, o);
    float inv = 1.0f / s;
#pragma unroll
    for (int t = 0; t < 7; t++) {
        int j = lane + 32 * t;
        if (j < SS) p[j] = vals[t] * inv;
    }
}

// ---------------- ctx = attn @ v (output tf32-rounded: feeds out-proj GEMM) ----------------
__global__ void __launch_bounds__(256) attn_ctx_kernel(const float* __restrict__ scores,
                                                       const float* __restrict__ qkv,
                                                       float* __restrict__ ctx)
{
    const int bh = blockIdx.y;
    const int b = bh / HEADS, h = bh - b * HEADS;
    const int i0 = blockIdx.x * 64;
    __shared__ float As[64][33];
    __shared__ __align__(16) float Vs[32][64];
    const int tx = threadIdx.x & 15, ty = threadIdx.x >> 4;
    const float* vbase = qkv + (size_t)b * SS * (3 * DD) + 2 * DD + h * HD;
    float acc[4][4];
#pragma unroll
    for (int i = 0; i < 4; i++)
#pragma unroll
        for (int j = 0; j < 4; j++) acc[i][j] = 0.f;

    for (int kt = 0; kt < 7; kt++) {
        int jb = kt * 32;
        for (int idx = threadIdx.x; idx < 2048; idx += 256) {
            int ii = idx >> 5, k = idx & 31;
            int i = i0 + ii, j = jb + k;
            As[ii][k] = (i < SS && j < SS) ? scores[((size_t)bh * SS + i) * SS + j] : 0.f;
        }
        for (int idx = threadIdx.x; idx < 2048; idx += 256) {
            int k = idx >> 6, d = idx & 63;
            int j = jb + k;
            Vs[k][d] = (j < SS) ? vbase[(size_t)j * (3 * DD) + d] : 0.f;
        }
        __syncthreads();
#pragma unroll 8
        for (int k = 0; k < 32; k++) {
            float4 b4 = *(const float4*)&Vs[k][tx * 4];
            float bb[4] = {b4.x, b4.y, b4.z, b4.w};
            float a[4];
#pragma unroll
            for (int rr = 0; rr < 4; rr++) a[rr] = As[ty * 4 + rr][k];
#pragma unroll
            for (int rr = 0; rr < 4; rr++)
#pragma unroll
                for (int cc = 0; cc < 4; cc++) acc[rr][cc] += a[rr] * bb[cc];
        }
        __syncthreads();
    }
#pragma unroll
    for (int rr = 0; rr < 4; rr++) {
        int i = i0 + ty * 4 + rr;
        if (i < SS) {
            float4 o = make_float4(tf32r(acc[rr][0]), tf32r(acc[rr][1]),
                                   tf32r(acc[rr][2]), tf32r(acc[rr][3]));
            *(float4*)&ctx[((size_t)b * SS + i) * DD + h * HD + tx * 4] = o;
        }
    }
}

// ---------------- classifier head ----------------
__global__ void head_kernel(const float* __restrict__ cls, const float* __restrict__ hw,
                            float* __restrict__ out)
{
    __shared__ float s[DD];
    int b = blockIdx.x;
    for (int k = threadIdx.x; k < DD; k += blockDim.x) s[k] = cls[(size_t)b * DD + k];
    __syncthreads();
    int c = threadIdx.x;
    if (c < NCLS) {
        const float* w = hw + (size_t)c * DD;
        float acc = 0.f;
#pragma unroll 8
        for (int k = 0; k < DD; k++) acc += s[k] * w[k];
        out[(size_t)b * NCLS + c] = acc;
    }
}

// ---------------- launch ----------------
extern "C" void kernel_launch(void* const* d_in, const int* in_sizes, int n_in,
                              void* d_out, int out_size) {
    const float* x         = (const float*)d_in[0];
    const float* patch_w   = (const float*)d_in[1];
    const float* patch_b   = (const float*)d_in[2];
    const float* cls_token = (const float*)d_in[3];
    const float* pos_embed = (const float*)d_in[4];
    const float* ln1_g     = (const float*)d_in[5];
    const float* ln1_b     = (const float*)d_in[6];
    const float* qkv_w     = (const float*)d_in[7];
    const float* qkv_b     = (const float*)d_in[8];
    const float* out_w     = (const float*)d_in[9];
    const float* out_b     = (const float*)d_in[10];
    const float* ln2_g     = (const float*)d_in[11];
    const float* ln2_b     = (const float*)d_in[12];
    const float* fc1_w     = (const float*)d_in[13];
    const float* fc1_b     = (const float*)d_in[14];
    const float* fc2_w     = (const float*)d_in[15];
    const float* fc2_b     = (const float*)d_in[16];
    const float* lnf_g     = (const float*)d_in[17];
    const float* lnf_b     = (const float*)d_in[18];
    const float* head_w    = (const float*)d_in[19];
    float* out = (float*)d_out;

    float *patches, *tok, *h, *xn, *qkv, *scores, *ctx, *hid, *cls, *w;
    cudaGetSymbolAddress((void**)&patches, g_patches);
    cudaGetSymbolAddress((void**)&tok, g_tok);
    cudaGetSymbolAddress((void**)&h, g_h);
    cudaGetSymbolAddress((void**)&xn, g_xn);
    cudaGetSymbolAddress((void**)&qkv, g_qkv);
    cudaGetSymbolAddress((void**)&scores, g_scores);
    cudaGetSymbolAddress((void**)&ctx, g_ctx);
    cudaGetSymbolAddress((void**)&hid, g_hid);
    cudaGetSymbolAddress((void**)&cls, g_cls);
    cudaGetSymbolAddress((void**)&w, g_w);

    // tf32-round all GEMM weights into scratch
    round4_kernel<<<(294912/4 + 255)/256, 256>>>(patch_w, w + W_PATCH, 294912/4);
    round4_kernel<<<(5308416/4 + 255)/256, 256>>>(qkv_w, w + W_QKV, 5308416/4);
    round4_kernel<<<(1769472/4 + 255)/256, 256>>>(out_w, w + W_OUT, 1769472/4);
    round4_kernel<<<(7077888/4 + 255)/256, 256>>>(fc1_w, w + W_FC1, 7077888/4);
    round4_kernel<<<(7077888/4 + 255)/256, 256>>>(fc2_w, w + W_FC2, 7077888/4);

    // patch embedding
    patchify_kernel<<<(PTOK * PATCH_DIM + 255) / 256, 256>>>(x, patches);
    gemm_tf32<0><<<dim3(DD / 128, PTOK / 128), 256>>>(
        patches, w + W_PATCH, patch_b, nullptr, tok, PTOK, DD, PATCH_DIM);
    assemble_kernel<<<(TOK * DD + 255) / 256, 256>>>(tok, cls_token, pos_embed, h);

    for (int i = 0; i < DEPTH; i++) {
        ln_kernel<<<TOK, DD>>>(h, ln1_g + i * DD, ln1_b + i * DD, xn, DD);
        gemm_tf32<0><<<dim3(3 * DD / 128, TOK / 128), 256>>>(
            xn, w + W_QKV + (size_t)i * 3 * DD * DD, qkv_b + (size_t)i * 3 * DD,
            nullptr, qkv, TOK, 3 * DD, DD);
        attn_scores_kernel<<<dim3(4, 4, BH), 256>>>(qkv, scores);
        softmax_kernel<<<(BH * SS + 7) / 8, 256>>>(scores, BH * SS);
        attn_ctx_kernel<<<dim3(4, BH), 256>>>(scores, qkv, ctx);
        gemm_tf32<2><<<dim3(DD / 128, TOK / 128), 256>>>(
            ctx, w + W_OUT + (size_t)i * DD * DD, out_b + (size_t)i * DD, h, h, TOK, DD, DD);
        ln_kernel<<<TOK, DD>>>(h, ln2_g + i * DD, ln2_b + i * DD, xn, DD);
        gemm_tf32<1><<<dim3(HID / 128, TOK / 128), 256>>>(
            xn, w + W_FC1 + (size_t)i * HID * DD, fc1_b + (size_t)i * HID,
            nullptr, hid, TOK, HID, DD);
        gemm_tf32<2><<<dim3(DD / 128, TOK / 128), 256>>>(
            hid, w + W_FC2 + (size_t)i * DD * HID, fc2_b + (size_t)i * DD, h, h, TOK, DD, HID);
    }

    ln_kernel<<<BB, DD>>>(h, lnf_g, lnf_b, cls, (long)SS * DD);
    head_kernel<<<BB, 128>>>(cls, head_w, out);
}